// round 2
// baseline (speedup 1.0000x reference)
#include <cuda_runtime.h>
#include <math.h>
#include <stdint.h>

#define T_STEPS 1024
#define BATCH   64
#define DIM     512
#define UNITS_  512
#define G3      1536
#define NCTA    128
#define TPB     256
#define UPC     4   // units per CTA

// ---------------- device scratch (no allocations allowed) ----------------
__device__ float g_xg0[(size_t)T_STEPS * BATCH * G3];   // x@W0+bi0, [t][b][g]
__device__ float g_h0[2][BATCH * UNITS_];
__device__ float g_h1[2][BATCH * UNITS_];
__device__ unsigned g_count;
__device__ volatile unsigned g_gen;

// ---------------- grid-wide barrier (all CTAs resident) ----------------
__device__ __forceinline__ void grid_barrier(unsigned target) {
    __syncthreads();
    if (threadIdx.x == 0) {
        __threadfence();
        unsigned arrived = atomicAdd(&g_count, 1u);
        if (arrived == NCTA - 1) {
            g_count = 0;
            __threadfence();
            atomicAdd((unsigned*)&g_gen, 1u);
        } else {
            while (g_gen < target) { }
        }
    }
    __syncthreads();
}

// ---------------- reset state each launch (graph-replay safe) ----------------
__global__ void reset_kernel() {
    if (blockIdx.x == 0 && threadIdx.x == 0) { g_count = 0; g_gen = 0; }
    int i = blockIdx.x * blockDim.x + threadIdx.x;
    int stride = gridDim.x * blockDim.x;
    for (int j = i; j < BATCH * UNITS_; j += stride) {
        g_h0[0][j] = 0.0f;
        g_h1[0][j] = 0.0f;
    }
}

// ---------------- phase 1: XG0[t][b][g] = x[b][t][:] @ W0 + bi0 ----------------
// grid: (24 g-tiles of 64, 1024 t), 256 threads, 4x4 per-thread microtile
__global__ void precompute_xg0(const float* __restrict__ x,
                               const float* __restrict__ W0,
                               const float* __restrict__ b0) {
    __shared__ float xs[32 * 68];  // [k][b], padded
    __shared__ float ws[32 * 68];  // [k][c], padded

    const int t     = blockIdx.y;
    const int gbase = blockIdx.x * 64;
    const int tid   = threadIdx.x;
    const int tr = tid & 15, tc = tid >> 4;
    const int r0 = tr * 4, c0 = tc * 4;

    float acc[4][4] = {};

    for (int kc = 0; kc < DIM; kc += 32) {
#pragma unroll
        for (int j = 0; j < 8; ++j) {
            int lin = tid + j * TPB;                 // 0..2047
            int bb = lin >> 5, klx = lin & 31;
            xs[klx * 68 + bb] =
                x[(size_t)bb * (T_STEPS * DIM) + (size_t)t * DIM + kc + klx];
            int kk = lin >> 6, cc = lin & 63;
            ws[kk * 68 + cc] =
                W0[(size_t)(kc + kk) * G3 + gbase + cc];
        }
        __syncthreads();
#pragma unroll
        for (int kk = 0; kk < 32; ++kk) {
            float4 a = *(const float4*)&xs[kk * 68 + r0];
            float4 b = *(const float4*)&ws[kk * 68 + c0];
            acc[0][0] += a.x * b.x; acc[0][1] += a.x * b.y; acc[0][2] += a.x * b.z; acc[0][3] += a.x * b.w;
            acc[1][0] += a.y * b.x; acc[1][1] += a.y * b.y; acc[1][2] += a.y * b.z; acc[1][3] += a.y * b.w;
            acc[2][0] += a.z * b.x; acc[2][1] += a.z * b.y; acc[2][2] += a.z * b.z; acc[2][3] += a.z * b.w;
            acc[3][0] += a.w * b.x; acc[3][1] += a.w * b.y; acc[3][2] += a.w * b.z; acc[3][3] += a.w * b.w;
        }
        __syncthreads();
    }

    float4 bias = *(const float4*)&b0[gbase + c0];   // b0 row 0 = input bias
#pragma unroll
    for (int rr = 0; rr < 4; ++rr) {
        size_t o = ((size_t)t * BATCH + r0 + rr) * G3 + gbase + c0;
        float4 v;
        v.x = acc[rr][0] + bias.x;
        v.y = acc[rr][1] + bias.y;
        v.z = acc[rr][2] + bias.z;
        v.w = acc[rr][3] + bias.w;
        *(float4*)&g_xg0[o] = v;
    }
}

// ---------------- phase 2: persistent recurrent loop ----------------
// 128 CTAs x 256 threads. thread = (r = batch row 0..63, ul = local unit 0..3).
// Each CTA owns units [4*bid, 4*bid+4): computes their 3 gate columns of every
// recurrent GEMM, then does the pointwise update for those units locally.
#define SMEM_FLOATS (3 * 6144 + 2 * 4352)
#define SMEM_BYTES  (SMEM_FLOATS * 4)

__global__ void __launch_bounds__(TPB, 1)
gru_loop(const float* __restrict__ U0, const float* __restrict__ W1,
         const float* __restrict__ U1, const float* __restrict__ b0,
         const float* __restrict__ b1, float* __restrict__ out) {
    extern __shared__ float sm[];
    float* wA  = sm;                 // U0 slice [g][ul][k]  (24 KB)
    float* wB  = sm + 6144;          // U1 slice
    float* wC  = sm + 12288;         // W1 slice
    float* hc0 = sm + 18432;         // h chunk [k][r] pad 68 (17 KB)
    float* hc1 = sm + 18432 + 4352;

    const int tid   = threadIdx.x;
    const int r     = tid & 63;
    const int ul    = tid >> 6;
    const int ubase = blockIdx.x * UPC;
    const int ug    = ubase + ul;

    // one-time weight preload (columns {ug, ug+512, ug+1024} for 4 local units)
    for (int idx = tid; idx < 6144; idx += TPB) {
        int k  = idx & 511;
        int gu = idx >> 9;          // g*4 + uu
        int g  = gu >> 2, uu = gu & 3;
        int col = g * 512 + ubase + uu;
        wA[idx] = __ldg(U0 + (size_t)k * G3 + col);
        wB[idx] = __ldg(U1 + (size_t)k * G3 + col);
        wC[idx] = __ldg(W1 + (size_t)k * G3 + col);
    }

    // per-thread bias registers (constant across steps)
    const float br0z = b0[G3 + ug], br0r = b0[G3 + 512 + ug], br0h = b0[G3 + 1024 + ug];
    const float bi1z = b1[ug],      bi1r = b1[512 + ug],      bi1h = b1[1024 + ug];
    const float br1z = b1[G3 + ug], br1r = b1[G3 + 512 + ug], br1h = b1[G3 + 1024 + ug];
    __syncthreads();

    const float* wAz = wA + ul * 512;
    const float* wAr = wA + (4 + ul) * 512;
    const float* wAh = wA + (8 + ul) * 512;
    const float* wBz = wB + ul * 512;
    const float* wBr = wB + (4 + ul) * 512;
    const float* wBh = wB + (8 + ul) * 512;
    const float* wCz = wC + ul * 512;
    const float* wCr = wC + (4 + ul) * 512;
    const float* wCh = wC + (8 + ul) * 512;

    unsigned gen = 0;

    for (int t = 0; t < T_STEPS; ++t) {
        const float* h0in  = g_h0[t & 1];
        float*       h0out = g_h0[(t + 1) & 1];
        const float* h1in  = g_h1[t & 1];
        float*       h1out = g_h1[(t + 1) & 1];

        // ---- GEMM_A: hg0 = h0 @ U0  and  hg1 = h1 @ U1 (12+12 cols/CTA) ----
        float az = 0.f, arr = 0.f, ah = 0.f;    // hg0 gates for (r, ug)
        float cz = 0.f, crr = 0.f, ch = 0.f;    // hg1 gates for (r, ug)
        for (int kc = 0; kc < DIM; kc += 64) {
#pragma unroll
            for (int j = 0; j < 16; ++j) {
                int lin = tid + j * TPB;         // 0..4095
                int rr2 = lin >> 6, klx = lin & 63;
                hc0[klx * 68 + rr2] = __ldcg(h0in + rr2 * 512 + kc + klx);
                hc1[klx * 68 + rr2] = __ldcg(h1in + rr2 * 512 + kc + klx);
            }
            __syncthreads();
            const float* hp0 = hc0 + r;
            const float* hp1 = hc1 + r;
#pragma unroll
            for (int kl = 0; kl < 64; kl += 4) {
                float4 wz0 = *(const float4*)(wAz + kc + kl);
                float4 wr0 = *(const float4*)(wAr + kc + kl);
                float4 wh0 = *(const float4*)(wAh + kc + kl);
                float4 wz1 = *(const float4*)(wBz + kc + kl);
                float4 wr1 = *(const float4*)(wBr + kc + kl);
                float4 wh1 = *(const float4*)(wBh + kc + kl);
                float a0 = hp0[(kl + 0) * 68], a1 = hp0[(kl + 1) * 68];
                float a2 = hp0[(kl + 2) * 68], a3 = hp0[(kl + 3) * 68];
                float e0 = hp1[(kl + 0) * 68], e1 = hp1[(kl + 1) * 68];
                float e2 = hp1[(kl + 2) * 68], e3 = hp1[(kl + 3) * 68];
                az  += a0 * wz0.x + a1 * wz0.y + a2 * wz0.z + a3 * wz0.w;
                arr += a0 * wr0.x + a1 * wr0.y + a2 * wr0.z + a3 * wr0.w;
                ah  += a0 * wh0.x + a1 * wh0.y + a2 * wh0.z + a3 * wh0.w;
                cz  += e0 * wz1.x + e1 * wz1.y + e2 * wz1.z + e3 * wz1.w;
                crr += e0 * wr1.x + e1 * wr1.y + e2 * wr1.z + e3 * wr1.w;
                ch  += e0 * wh1.x + e1 * wh1.y + e2 * wh1.z + e3 * wh1.w;
            }
            __syncthreads();
        }

        // ---- pointwise layer 0 (local units only, no sync needed) ----
        {
            size_t xb = ((size_t)t * BATCH + r) * G3 + ug;
            float xz = __ldg(&g_xg0[xb]);
            float xr = __ldg(&g_xg0[xb + 512]);
            float xh = __ldg(&g_xg0[xb + 1024]);
            float z  = 1.f / (1.f + expf(-(xz + az + br0z)));
            float rg = 1.f / (1.f + expf(-(xr + arr + br0r)));
            float cand = tanhf(xh + rg * (ah + br0h));
            float h0o = __ldcg(h0in + r * 512 + ug);
            float h0n = z * h0o + (1.f - z) * cand;
            h0out[r * 512 + ug] = h0n;
        }

        grid_barrier(++gen);   // publish h0_new

        // ---- GEMM_B: xg1 = h0_new @ W1 (12 cols/CTA) ----
        float bz = 0.f, bxr = 0.f, bxh = 0.f;
        for (int kc = 0; kc < DIM; kc += 64) {
#pragma unroll
            for (int j = 0; j < 16; ++j) {
                int lin = tid + j * TPB;
                int rr2 = lin >> 6, klx = lin & 63;
                hc0[klx * 68 + rr2] = __ldcg(h0out + rr2 * 512 + kc + klx);
            }
            __syncthreads();
            const float* hp0 = hc0 + r;
#pragma unroll
            for (int kl = 0; kl < 64; kl += 4) {
                float4 wz = *(const float4*)(wCz + kc + kl);
                float4 wr = *(const float4*)(wCr + kc + kl);
                float4 wh = *(const float4*)(wCh + kc + kl);
                float a0 = hp0[(kl + 0) * 68], a1 = hp0[(kl + 1) * 68];
                float a2 = hp0[(kl + 2) * 68], a3 = hp0[(kl + 3) * 68];
                bz  += a0 * wz.x + a1 * wz.y + a2 * wz.z + a3 * wz.w;
                bxr += a0 * wr.x + a1 * wr.y + a2 * wr.z + a3 * wr.w;
                bxh += a0 * wh.x + a1 * wh.y + a2 * wh.z + a3 * wh.w;
            }
            __syncthreads();
        }

        // ---- pointwise layer 1 ----
        {
            float z1 = 1.f / (1.f + expf(-((bz  + bi1z) + (cz  + br1z))));
            float r1 = 1.f / (1.f + expf(-((bxr + bi1r) + (crr + br1r))));
            float cand1 = tanhf((bxh + bi1h) + r1 * (ch + br1h));
            float h1o = __ldcg(h1in + r * 512 + ug);
            float h1n = z1 * h1o + (1.f - z1) * cand1;
            h1out[r * 512 + ug] = h1n;
            if (t == T_STEPS - 1) out[r * 512 + ug] = h1n;
        }

        grid_barrier(++gen);   // publish h1_new (and gate next step)
    }
}

// ---------------- launcher ----------------
extern "C" void kernel_launch(void* const* d_in, const int* in_sizes, int n_in,
                              void* d_out, int out_size) {
    const float* x  = (const float*)d_in[0];
    const float* W0 = (const float*)d_in[1];
    const float* U0 = (const float*)d_in[2];
    const float* b0 = (const float*)d_in[3];
    const float* W1 = (const float*)d_in[4];
    const float* U1 = (const float*)d_in[5];
    const float* b1 = (const float*)d_in[6];
    float* out = (float*)d_out;

    cudaFuncSetAttribute(gru_loop, cudaFuncAttributeMaxDynamicSharedMemorySize,
                         SMEM_BYTES);

    reset_kernel<<<32, 256>>>();
    precompute_xg0<<<dim3(24, 1024), TPB>>>(x, W0, b0);
    gru_loop<<<NCTA, TPB, SMEM_BYTES>>>(U0, W1, U1, b0, b1, out);
}

// round 3
// speedup vs baseline: 1.0029x; 1.0029x over previous
#include <cuda_runtime.h>
#include <math.h>
#include <stdint.h>

#define T_STEPS 1024
#define BATCH   64
#define DIM     512
#define UNITS_  512
#define G3      1536
#define NCTA    128
#define TPB     256
#define UPC     4   // units per CTA

// ---------------- device scratch (no allocations allowed) ----------------
__device__ float g_xg0[(size_t)T_STEPS * BATCH * G3];   // x@W0+bi0, [t][b][g]
__device__ float g_h0[2][BATCH * UNITS_];
__device__ float g_h1[2][BATCH * UNITS_];
__device__ unsigned g_count;
__device__ volatile unsigned g_gen;

// ---------------- grid-wide barrier (all CTAs resident) ----------------
__device__ __forceinline__ void grid_barrier(unsigned target) {
    __syncthreads();
    if (threadIdx.x == 0) {
        __threadfence();
        unsigned arrived = atomicAdd(&g_count, 1u);
        if (arrived == NCTA - 1) {
            g_count = 0;
            __threadfence();
            atomicAdd((unsigned*)&g_gen, 1u);
        } else {
            while (g_gen < target) { }
        }
    }
    __syncthreads();
}

// ---------------- reset state each launch (graph-replay safe) ----------------
__global__ void reset_kernel() {
    if (blockIdx.x == 0 && threadIdx.x == 0) { g_count = 0; g_gen = 0; }
    int i = blockIdx.x * blockDim.x + threadIdx.x;
    int stride = gridDim.x * blockDim.x;
    for (int j = i; j < BATCH * UNITS_; j += stride) {
        g_h0[0][j] = 0.0f;
        g_h1[0][j] = 0.0f;
    }
}

// ---------------- phase 1: XG0[t][b][g] = x[b][t][:] @ W0 + bi0 ----------------
// grid: (24 g-tiles of 64, 1024 t), 256 threads, 4x4 per-thread microtile
__global__ void precompute_xg0(const float* __restrict__ x,
                               const float* __restrict__ W0,
                               const float* __restrict__ b0) {
    __shared__ float xs[32 * 68];  // [k][b], padded
    __shared__ float ws[32 * 68];  // [k][c], padded

    const int t     = blockIdx.y;
    const int gbase = blockIdx.x * 64;
    const int tid   = threadIdx.x;
    const int tr = tid & 15, tc = tid >> 4;
    const int r0 = tr * 4, c0 = tc * 4;

    float acc[4][4] = {};

    for (int kc = 0; kc < DIM; kc += 32) {
#pragma unroll
        for (int j = 0; j < 8; ++j) {
            int lin = tid + j * TPB;                 // 0..2047
            int bb = lin >> 5, klx = lin & 31;
            xs[klx * 68 + bb] =
                x[(size_t)bb * (T_STEPS * DIM) + (size_t)t * DIM + kc + klx];
            int kk = lin >> 6, cc = lin & 63;
            ws[kk * 68 + cc] =
                W0[(size_t)(kc + kk) * G3 + gbase + cc];
        }
        __syncthreads();
#pragma unroll
        for (int kk = 0; kk < 32; ++kk) {
            float4 a = *(const float4*)&xs[kk * 68 + r0];
            float4 b = *(const float4*)&ws[kk * 68 + c0];
            acc[0][0] += a.x * b.x; acc[0][1] += a.x * b.y; acc[0][2] += a.x * b.z; acc[0][3] += a.x * b.w;
            acc[1][0] += a.y * b.x; acc[1][1] += a.y * b.y; acc[1][2] += a.y * b.z; acc[1][3] += a.y * b.w;
            acc[2][0] += a.z * b.x; acc[2][1] += a.z * b.y; acc[2][2] += a.z * b.z; acc[2][3] += a.z * b.w;
            acc[3][0] += a.w * b.x; acc[3][1] += a.w * b.y; acc[3][2] += a.w * b.z; acc[3][3] += a.w * b.w;
        }
        __syncthreads();
    }

    float4 bias = *(const float4*)&b0[gbase + c0];   // b0 row 0 = input bias
#pragma unroll
    for (int rr = 0; rr < 4; ++rr) {
        size_t o = ((size_t)t * BATCH + r0 + rr) * G3 + gbase + c0;
        float4 v;
        v.x = acc[rr][0] + bias.x;
        v.y = acc[rr][1] + bias.y;
        v.z = acc[rr][2] + bias.z;
        v.w = acc[rr][3] + bias.w;
        *(float4*)&g_xg0[o] = v;
    }
}

// ---------------- phase 2: persistent recurrent loop ----------------
// 128 CTAs x 256 threads. thread = (r = batch row 0..63, ul = local unit 0..3).
// Each CTA owns units [4*bid, 4*bid+4): computes their 3 gate columns of every
// recurrent GEMM, then does the pointwise update for those units locally.
#define SMEM_FLOATS (3 * 6144 + 2 * 4352)
#define SMEM_BYTES  (SMEM_FLOATS * 4)

__global__ void __launch_bounds__(TPB, 1)
gru_loop(const float* __restrict__ U0, const float* __restrict__ W1,
         const float* __restrict__ U1, const float* __restrict__ b0,
         const float* __restrict__ b1, float* __restrict__ out) {
    extern __shared__ float sm[];
    float* wA  = sm;                 // U0 slice [g][ul][k]  (24 KB)
    float* wB  = sm + 6144;          // U1 slice
    float* wC  = sm + 12288;         // W1 slice
    float* hc0 = sm + 18432;         // h chunk [k][r] pad 68 (17 KB)
    float* hc1 = sm + 18432 + 4352;

    const int tid   = threadIdx.x;
    const int r     = tid & 63;
    const int ul    = tid >> 6;
    const int ubase = blockIdx.x * UPC;
    const int ug    = ubase + ul;

    // one-time weight preload (columns {ug, ug+512, ug+1024} for 4 local units)
    for (int idx = tid; idx < 6144; idx += TPB) {
        int k  = idx & 511;
        int gu = idx >> 9;          // g*4 + uu
        int g  = gu >> 2, uu = gu & 3;
        int col = g * 512 + ubase + uu;
        wA[idx] = __ldg(U0 + (size_t)k * G3 + col);
        wB[idx] = __ldg(U1 + (size_t)k * G3 + col);
        wC[idx] = __ldg(W1 + (size_t)k * G3 + col);
    }

    // per-thread bias registers (constant across steps)
    const float br0z = b0[G3 + ug], br0r = b0[G3 + 512 + ug], br0h = b0[G3 + 1024 + ug];
    const float bi1z = b1[ug],      bi1r = b1[512 + ug],      bi1h = b1[1024 + ug];
    const float br1z = b1[G3 + ug], br1r = b1[G3 + 512 + ug], br1h = b1[G3 + 1024 + ug];
    __syncthreads();

    const float* wAz = wA + ul * 512;
    const float* wAr = wA + (4 + ul) * 512;
    const float* wAh = wA + (8 + ul) * 512;
    const float* wBz = wB + ul * 512;
    const float* wBr = wB + (4 + ul) * 512;
    const float* wBh = wB + (8 + ul) * 512;
    const float* wCz = wC + ul * 512;
    const float* wCr = wC + (4 + ul) * 512;
    const float* wCh = wC + (8 + ul) * 512;

    unsigned gen = 0;

    for (int t = 0; t < T_STEPS; ++t) {
        const float* h0in  = g_h0[t & 1];
        float*       h0out = g_h0[(t + 1) & 1];
        const float* h1in  = g_h1[t & 1];
        float*       h1out = g_h1[(t + 1) & 1];

        // ---- GEMM_A: hg0 = h0 @ U0  and  hg1 = h1 @ U1 (12+12 cols/CTA) ----
        float az = 0.f, arr = 0.f, ah = 0.f;    // hg0 gates for (r, ug)
        float cz = 0.f, crr = 0.f, ch = 0.f;    // hg1 gates for (r, ug)
        for (int kc = 0; kc < DIM; kc += 64) {
#pragma unroll
            for (int j = 0; j < 16; ++j) {
                int lin = tid + j * TPB;         // 0..4095
                int rr2 = lin >> 6, klx = lin & 63;
                hc0[klx * 68 + rr2] = __ldcg(h0in + rr2 * 512 + kc + klx);
                hc1[klx * 68 + rr2] = __ldcg(h1in + rr2 * 512 + kc + klx);
            }
            __syncthreads();
            const float* hp0 = hc0 + r;
            const float* hp1 = hc1 + r;
#pragma unroll
            for (int kl = 0; kl < 64; kl += 4) {
                float4 wz0 = *(const float4*)(wAz + kc + kl);
                float4 wr0 = *(const float4*)(wAr + kc + kl);
                float4 wh0 = *(const float4*)(wAh + kc + kl);
                float4 wz1 = *(const float4*)(wBz + kc + kl);
                float4 wr1 = *(const float4*)(wBr + kc + kl);
                float4 wh1 = *(const float4*)(wBh + kc + kl);
                float a0 = hp0[(kl + 0) * 68], a1 = hp0[(kl + 1) * 68];
                float a2 = hp0[(kl + 2) * 68], a3 = hp0[(kl + 3) * 68];
                float e0 = hp1[(kl + 0) * 68], e1 = hp1[(kl + 1) * 68];
                float e2 = hp1[(kl + 2) * 68], e3 = hp1[(kl + 3) * 68];
                az  += a0 * wz0.x + a1 * wz0.y + a2 * wz0.z + a3 * wz0.w;
                arr += a0 * wr0.x + a1 * wr0.y + a2 * wr0.z + a3 * wr0.w;
                ah  += a0 * wh0.x + a1 * wh0.y + a2 * wh0.z + a3 * wh0.w;
                cz  += e0 * wz1.x + e1 * wz1.y + e2 * wz1.z + e3 * wz1.w;
                crr += e0 * wr1.x + e1 * wr1.y + e2 * wr1.z + e3 * wr1.w;
                ch  += e0 * wh1.x + e1 * wh1.y + e2 * wh1.z + e3 * wh1.w;
            }
            __syncthreads();
        }

        // ---- pointwise layer 0 (local units only, no sync needed) ----
        {
            size_t xb = ((size_t)t * BATCH + r) * G3 + ug;
            float xz = __ldg(&g_xg0[xb]);
            float xr = __ldg(&g_xg0[xb + 512]);
            float xh = __ldg(&g_xg0[xb + 1024]);
            float z  = 1.f / (1.f + expf(-(xz + az + br0z)));
            float rg = 1.f / (1.f + expf(-(xr + arr + br0r)));
            float cand = tanhf(xh + rg * (ah + br0h));
            float h0o = __ldcg(h0in + r * 512 + ug);
            float h0n = z * h0o + (1.f - z) * cand;
            h0out[r * 512 + ug] = h0n;
        }

        grid_barrier(++gen);   // publish h0_new

        // ---- GEMM_B: xg1 = h0_new @ W1 (12 cols/CTA) ----
        float bz = 0.f, bxr = 0.f, bxh = 0.f;
        for (int kc = 0; kc < DIM; kc += 64) {
#pragma unroll
            for (int j = 0; j < 16; ++j) {
                int lin = tid + j * TPB;
                int rr2 = lin >> 6, klx = lin & 63;
                hc0[klx * 68 + rr2] = __ldcg(h0out + rr2 * 512 + kc + klx);
            }
            __syncthreads();
            const float* hp0 = hc0 + r;
#pragma unroll
            for (int kl = 0; kl < 64; kl += 4) {
                float4 wz = *(const float4*)(wCz + kc + kl);
                float4 wr = *(const float4*)(wCr + kc + kl);
                float4 wh = *(const float4*)(wCh + kc + kl);
                float a0 = hp0[(kl + 0) * 68], a1 = hp0[(kl + 1) * 68];
                float a2 = hp0[(kl + 2) * 68], a3 = hp0[(kl + 3) * 68];
                bz  += a0 * wz.x + a1 * wz.y + a2 * wz.z + a3 * wz.w;
                bxr += a0 * wr.x + a1 * wr.y + a2 * wr.z + a3 * wr.w;
                bxh += a0 * wh.x + a1 * wh.y + a2 * wh.z + a3 * wh.w;
            }
            __syncthreads();
        }

        // ---- pointwise layer 1 ----
        {
            float z1 = 1.f / (1.f + expf(-((bz  + bi1z) + (cz  + br1z))));
            float r1 = 1.f / (1.f + expf(-((bxr + bi1r) + (crr + br1r))));
            float cand1 = tanhf((bxh + bi1h) + r1 * (ch + br1h));
            float h1o = __ldcg(h1in + r * 512 + ug);
            float h1n = z1 * h1o + (1.f - z1) * cand1;
            h1out[r * 512 + ug] = h1n;
            if (t == T_STEPS - 1) out[r * 512 + ug] = h1n;
        }

        grid_barrier(++gen);   // publish h1_new (and gate next step)
    }
}

// ---------------- launcher ----------------
extern "C" void kernel_launch(void* const* d_in, const int* in_sizes, int n_in,
                              void* d_out, int out_size) {
    const float* x  = (const float*)d_in[0];
    const float* W0 = (const float*)d_in[1];
    const float* U0 = (const float*)d_in[2];
    const float* b0 = (const float*)d_in[3];
    const float* W1 = (const float*)d_in[4];
    const float* U1 = (const float*)d_in[5];
    const float* b1 = (const float*)d_in[6];
    float* out = (float*)d_out;

    cudaFuncSetAttribute(gru_loop, cudaFuncAttributeMaxDynamicSharedMemorySize,
                         SMEM_BYTES);

    reset_kernel<<<32, 256>>>();
    precompute_xg0<<<dim3(24, 1024), TPB>>>(x, W0, b0);
    gru_loop<<<NCTA, TPB, SMEM_BYTES>>>(U0, W1, U1, b0, b1, out);
}